// round 16
// baseline (speedup 1.0000x reference)
#include <cuda_runtime.h>
#include <math.h>

#define Bsz    2048
#define Hd     256
#define INd    64
#define KTERMS 8
#define ROWS   14          // rows per CTA (7 f32x2 pairs)
#define NCTAS  148
#define NTHR   512
#define PITCH  20          // floats per smem act row (80B, odd 16B-granule stride)
#define SLOT   34          // u64 per export slot (272B, odd 16B-granule stride)

typedef unsigned long long ull;

// Pre-transposed weights (L2-resident)
__device__ float g_whT[Hd*Hd];     // whT[j*Hd+k]   = wh[k*Hd+j]
__device__ float g_woutT[Hd*Hd];   // woutT[j*Hd+k] = wout[k*Hd+j]
__device__ float g_wxT[INd*Hd];    // wxT[i*Hd+k]   = wx[k*INd+i]

// ---------------- packed f32x2 helpers ----------------
__device__ __forceinline__ ull pack2(float lo, float hi) {
    ull r; asm("mov.b64 %0, {%1,%2};" : "=l"(r) : "f"(lo), "f"(hi)); return r;
}
__device__ __forceinline__ void unpack2(ull v, float& lo, float& hi) {
    asm("mov.b64 {%0,%1}, %2;" : "=f"(lo), "=f"(hi) : "l"(v));
}
__device__ __forceinline__ ull fma2(ull a, ull b, ull c) {
    ull d; asm("fma.rn.f32x2 %0, %1, %2, %3;" : "=l"(d) : "l"(a), "l"(b), "l"(c)); return d;
}
__device__ __forceinline__ ull mul2(ull a, ull b) {
    ull d; asm("mul.rn.f32x2 %0, %1, %2;" : "=l"(d) : "l"(a), "l"(b)); return d;
}
__device__ __forceinline__ ull add2(ull a, ull b) {
    ull d; asm("add.rn.f32x2 %0, %1, %2;" : "=l"(d) : "l"(a), "l"(b)); return d;
}

// load 7 u64 (14 floats) from an act row
__device__ __forceinline__ void ldrow7(const float* p, ull v[7]) {
    const ulonglong2* q = reinterpret_cast<const ulonglong2*>(p);
    ulonglong2 a = q[0], b = q[1], c = q[2];
    v[0]=a.x; v[1]=a.y; v[2]=b.x; v[3]=b.y; v[4]=c.x; v[5]=c.y;
    v[6] = reinterpret_cast<const ull*>(p)[6];
}

// C=4, G=8 partial GEMM for j-group g: j = 8m+g, phys(j) = m + NJ*g.
// ONE float4 weight load feeds 4 columns x 7 row-pairs = 28 FFMA2 per j.
template<int NJ>
__device__ __forceinline__ void gemm7(const float* __restrict__ Wt, int col0, int g,
                                      const float* sIn, ull acc[28]) {
    const float* wp = Wt + g * Hd + col0;
    const float* sp = sIn + (NJ * g) * PITCH;
#pragma unroll 4
    for (int m = 0; m < NJ; ++m) {
        float4 w4 = *reinterpret_cast<const float4*>(wp);
        ull v[7];
        ldrow7(sp, v);
        ull w0 = pack2(w4.x, w4.x), w1 = pack2(w4.y, w4.y);
        ull w2 = pack2(w4.z, w4.z), w3 = pack2(w4.w, w4.w);
#pragma unroll
        for (int t = 0; t < 7; ++t) {
            acc[t]      = fma2(w0, v[t], acc[t]);
            acc[7 + t]  = fma2(w1, v[t], acc[7 + t]);
            acc[14 + t] = fma2(w2, v[t], acc[14 + t]);
            acc[21 + t] = fma2(w3, v[t], acc[21 + t]);
        }
        wp += 8 * Hd;
        sp += PITCH;
    }
}

// export 28 u64: col c at u64 offset c*8 (pairs 0..6)
__device__ __forceinline__ void exportP(ull* p, const ull acc[28]) {
#pragma unroll
    for (int c = 0; c < 4; ++c) {
        ull* b = p + c * 8;
        reinterpret_cast<ulonglong2*>(b)[0] = make_ulonglong2(acc[c*7+0], acc[c*7+1]);
        reinterpret_cast<ulonglong2*>(b)[1] = make_ulonglong2(acc[c*7+2], acc[c*7+3]);
        reinterpret_cast<ulonglong2*>(b)[2] = make_ulonglong2(acc[c*7+4], acc[c*7+5]);
        b[6] = acc[c*7+6];
    }
}

// merge across 8 groups. HALF=0: pairs 0..3 (m[0..3]); HALF=1: pairs 4..6 (m[0..2]).
template<int HALF>
__device__ __forceinline__ void mergeP(const ull* sRed, int quadm, int moff, ull m[4]) {
    m[0] = m[1] = m[2] = m[3] = 0ull;
#pragma unroll
    for (int gp = 0; gp < 8; ++gp) {
        const ull* p = sRed + (gp * 64 + quadm) * SLOT + moff;
        ulonglong2 a = reinterpret_cast<const ulonglong2*>(p)[0];
        m[0] = add2(m[0], a.x); m[1] = add2(m[1], a.y);
        if (HALF == 0) {
            ulonglong2 b = reinterpret_cast<const ulonglong2*>(p)[1];
            m[2] = add2(m[2], b.x); m[3] = add2(m[3], b.y);
        } else {
            m[2] = add2(m[2], p[2]);
        }
    }
}

// store merged slice to act row (HALF=0: u64 0..3, HALF=1: u64 4..6)
template<int HALF>
__device__ __forceinline__ void st_slice(float* rowbase, const ull m[4]) {
    ull* p = reinterpret_cast<ull*>(rowbase) + HALF * 4;
    reinterpret_cast<ulonglong2*>(p)[0] = make_ulonglong2(m[0], m[1]);
    if (HALF == 0) reinterpret_cast<ulonglong2*>(p)[1] = make_ulonglong2(m[2], m[3]);
    else           p[2] = m[2];
}

// ---------------- merged transpose ----------------
__global__ void transpose_all(const float* __restrict__ wh,
                              const float* __restrict__ wout,
                              const float* __restrict__ wx) {
    __shared__ float tile[32][33];
    int b = blockIdx.x;
    const float* in; float* out; int rows, cols, bx;
    if (b < 64)       { in = wh;   out = g_whT;   rows = Hd; cols = Hd;  bx = b; }
    else if (b < 128) { in = wout; out = g_woutT; rows = Hd; cols = Hd;  bx = b - 64; }
    else              { in = wx;   out = g_wxT;   rows = Hd; cols = INd; bx = b - 128; }
    int nbx = cols / 32;
    int c0 = (bx % nbx) * 32, r0 = (bx / nbx) * 32;
    for (int dy = threadIdx.y; dy < 32; dy += 8)
        tile[dy][threadIdx.x] = in[(r0 + dy) * cols + (c0 + threadIdx.x)];
    __syncthreads();
    for (int dy = threadIdx.y; dy < 32; dy += 8)
        out[(c0 + dy) * rows + (r0 + threadIdx.x)] = tile[threadIdx.x][dy];
}

// ---------------- pipeline (templated on merge half) ----------------
template<int HALF>
__device__ __forceinline__ void pipeline(
    int g, int col0, int mycol, int row0, ull* myslot, ull* sRed,
    float* sA, float* sB, float* sXx, float* sXd,
    const float* __restrict__ b0, const float* __restrict__ b1,
    float* __restrict__ out) {

    const int NP     = (HALF == 0) ? 4 : 3;
    const int quadm  = mycol >> 2;
    const int moff   = (mycol & 3) * 8 + HALF * 4;
    const int myphys = (mycol >> 3) + ((mycol & 7) << 5);   // phys(mycol), mod-8 perm
    float* rowA = sA + myphys * PITCH;
    float* rowB = sB + myphys * PITCH;

    float bk0 = b0[mycol];
    float bk1 = b1[mycol];

    ull gate[4], dth[4], hd[4];
    ull acc[28];

    // ---- P1: l1 = x@wxT + h@whT + b0 -> gate, relu -> sB
#pragma unroll
    for (int q = 0; q < 28; ++q) acc[q] = 0ull;
    gemm7<8>(g_wxT, col0, g, sXx, acc);
    gemm7<32>(g_whT, col0, g, sA, acc);
    exportP(myslot, acc);
    __syncthreads();
    {
        ull m[4], relu[4];
        mergeP<HALF>(sRed, quadm, moff, m);
        ull bp = pack2(bk0, bk0);
#pragma unroll
        for (int t = 0; t < NP; ++t) {
            m[t] = add2(m[t], bp);
            float a, b; unpack2(m[t], a, b);
            float ga = (a > 0.f) ? 1.f : 0.f;
            float gb = (b > 0.f) ? 1.f : 0.f;
            gate[t] = pack2(ga, gb);
            relu[t] = pack2(ga * a, gb * b);
        }
        st_slice<HALF>(rowB, relu);
    }
    __syncthreads();

    // ---- P2: uu = xdot@wxT ; gated-u -> sA
#pragma unroll
    for (int q = 0; q < 28; ++q) acc[q] = 0ull;
    gemm7<8>(g_wxT, col0, g, sXd, acc);
    exportP(myslot, acc);
    __syncthreads();
    {
        ull m[4];
        mergeP<HALF>(sRed, quadm, moff, m);
#pragma unroll
        for (int t = 0; t < NP; ++t) m[t] = mul2(m[t], gate[t]);
        st_slice<HALF>(rowA, m);
    }
    __syncthreads();

    // ---- P3: lout = relu@woutT + b1 -> dth
#pragma unroll
    for (int q = 0; q < 28; ++q) acc[q] = 0ull;
    gemm7<32>(g_woutT, col0, g, sB, acc);
    exportP(myslot, acc);
    __syncthreads();
    {
        ull m[4];
        mergeP<HALF>(sRed, quadm, moff, m);
        ull bp = pack2(bk1, bk1);
#pragma unroll
        for (int t = 0; t < NP; ++t) {
            ull L = add2(m[t], bp);
            float a, b; unpack2(L, a, b);
            float ta = tanhf(a), tb = tanhf(b);
            dth[t] = pack2(1.f - ta * ta, 1.f - tb * tb);
        }
    }
    __syncthreads();

    // ---- P4: jx = gated-u@woutT ; curr = dth*jx -> sA ; hd = curr
#pragma unroll
    for (int q = 0; q < 28; ++q) acc[q] = 0ull;
    gemm7<32>(g_woutT, col0, g, sA, acc);
    exportP(myslot, acc);
    __syncthreads();
    {
        ull m[4];
        mergeP<HALF>(sRed, quadm, moff, m);
#pragma unroll
        for (int t = 0; t < NP; ++t) { m[t] = mul2(m[t], dth[t]); hd[t] = m[t]; }
        st_slice<HALF>(rowA, m);
    }
    __syncthreads();

    // ---- 8 Jh-power iterations: curr = dth * ((gate * (curr@whT)) @ woutT)
    for (int it = 0; it < KTERMS; ++it) {
#pragma unroll
        for (int q = 0; q < 28; ++q) acc[q] = 0ull;
        gemm7<32>(g_whT, col0, g, sA, acc);
        exportP(myslot, acc);
        __syncthreads();
        {
            ull m[4];
            mergeP<HALF>(sRed, quadm, moff, m);
#pragma unroll
            for (int t = 0; t < NP; ++t) m[t] = mul2(m[t], gate[t]);
            st_slice<HALF>(rowB, m);
        }
        __syncthreads();
#pragma unroll
        for (int q = 0; q < 28; ++q) acc[q] = 0ull;
        gemm7<32>(g_woutT, col0, g, sB, acc);
        exportP(myslot, acc);
        __syncthreads();
        {
            ull m[4];
            mergeP<HALF>(sRed, quadm, moff, m);
#pragma unroll
            for (int t = 0; t < NP; ++t) { m[t] = mul2(m[t], dth[t]); hd[t] = add2(hd[t], m[t]); }
            st_slice<HALF>(rowA, m);
        }
        __syncthreads();
    }

    // ---- write h_dot (HALF 0: rows row0..+7 ; HALF 1: rows row0+8..+13), guard tail
#pragma unroll
    for (int t = 0; t < NP; ++t) {
        float a, b; unpack2(hd[t], a, b);
        int r = row0 + HALF * 8 + 2 * t;
        if (r < Bsz)     out[r       * Hd + mycol] = a;
        if (r + 1 < Bsz) out[(r + 1) * Hd + mycol] = b;
    }
}

// ---------------- fused kernel: 512 thr, G=8, C=4, 1 CTA/SM ----------------
__global__ void __launch_bounds__(NTHR, 1)
fused_kernel(const float* __restrict__ hin, const float* __restrict__ xin,
             const float* __restrict__ xdin, const float* __restrict__ b0,
             const float* __restrict__ b1, float* __restrict__ out) {
    extern __shared__ __align__(16) char smraw[];
    ull*   sRed = reinterpret_cast<ull*>(smraw);                 // [512][SLOT] 139264B
    float* sA   = reinterpret_cast<float*>(sRed + NTHR * SLOT);  // [256][PITCH]
    float* sB   = sA + Hd * PITCH;                               // [256][PITCH]
    float* sXx  = sB + Hd * PITCH;                               // [64][PITCH]
    float* sXd  = sXx + INd * PITCH;                             // [64][PITCH]

    const int bid  = blockIdx.x;
    const int row0 = bid * ROWS;
    if (row0 >= Bsz) return;                                     // bid 147 idle

    const int tid  = threadIdx.x;
    const int warp = tid >> 5;
    const int lane = tid & 31;
    const int g    = warp >> 1;                  // j-group 0..7 (warp-uniform, 2 warps each)
    const int ct   = ((warp & 1) << 5) + lane;   // col-thread 0..63; owns cols 4ct..4ct+3
    const int col0 = ct << 2;
    ull* myslot = sRed + (g * 64 + ct) * SLOT;

    const int mycol = tid & 255;                 // merge/pointwise ownership
    const int half  = tid >> 8;                  // 0: pairs 0-3, 1: pairs 4-6

    // ---- stage inputs (transposed + phys-permuted mod 8); clamp tail rows
    for (int e = tid; e < ROWS * Hd; e += NTHR) {
        int r = e >> 8, j = e & 255;
        int rr = row0 + r; if (rr > Bsz - 1) rr = Bsz - 1;
        int pr = (j >> 3) + ((j & 7) << 5);
        sA[pr * PITCH + r] = hin[rr * Hd + j];
    }
    for (int e = tid; e < ROWS * INd; e += NTHR) {
        int r = e >> 6, i = e & 63;
        int rr = row0 + r; if (rr > Bsz - 1) rr = Bsz - 1;
        int pr = (i >> 3) + ((i & 7) << 3);
        sXx[pr * PITCH + r] = xin[rr * INd + i];
        sXd[pr * PITCH + r] = xdin[rr * INd + i];
    }
    __syncthreads();

    if (half == 0)
        pipeline<0>(g, col0, mycol, row0, myslot, sRed, sA, sB, sXx, sXd, b0, b1, out);
    else
        pipeline<1>(g, col0, mycol, row0, myslot, sRed, sA, sB, sXx, sXd, b0, b1, out);
}

#define SMEM_BYTES (NTHR * SLOT * 8 + (2 * Hd + 2 * INd) * PITCH * 4)

extern "C" void kernel_launch(void* const* d_in, const int* in_sizes, int n_in,
                              void* d_out, int out_size) {
    (void)in_sizes; (void)n_in; (void)out_size;
    const float* h_   = (const float*)d_in[0];
    const float* x    = (const float*)d_in[1];
    const float* xdot = (const float*)d_in[2];
    const float* wx   = (const float*)d_in[3];
    const float* wh   = (const float*)d_in[4];
    const float* wout = (const float*)d_in[5];
    const float* b0   = (const float*)d_in[6];
    const float* b1   = (const float*)d_in[7];
    float* out = (float*)d_out;

    cudaFuncSetAttribute(fused_kernel, cudaFuncAttributeMaxDynamicSharedMemorySize, SMEM_BYTES);
    transpose_all<<<144, dim3(32, 8)>>>(wh, wout, wx);
    fused_kernel<<<NCTAS, NTHR, SMEM_BYTES>>>(h_, x, xdot, b0, b1, out);
}

// round 17
// speedup vs baseline: 1.1316x; 1.1316x over previous
#include <cuda_runtime.h>
#include <math.h>

#define Bsz    2048
#define Hd     256
#define INd    64
#define KTERMS 8
#define NTHR   256
#define PITCH  12          // floats per smem act row (48B, odd 16B-granule stride)
#define SLOT   18          // u64 per export slot (144B, odd 16B-granule stride)

typedef unsigned long long ull;

// Pre-transposed weights (L2-resident)
__device__ float g_whT[Hd*Hd];
__device__ float g_woutT[Hd*Hd];
__device__ float g_wxT[INd*Hd];

// ---------------- packed f32x2 helpers ----------------
__device__ __forceinline__ ull pack2(float lo, float hi) {
    ull r; asm("mov.b64 %0, {%1,%2};" : "=l"(r) : "f"(lo), "f"(hi)); return r;
}
__device__ __forceinline__ void unpack2(ull v, float& lo, float& hi) {
    asm("mov.b64 {%0,%1}, %2;" : "=f"(lo), "=f"(hi) : "l"(v));
}
__device__ __forceinline__ ull fma2(ull a, ull b, ull c) {
    ull d; asm("fma.rn.f32x2 %0, %1, %2, %3;" : "=l"(d) : "l"(a), "l"(b), "l"(c)); return d;
}
__device__ __forceinline__ ull mul2(ull a, ull b) {
    ull d; asm("mul.rn.f32x2 %0, %1, %2;" : "=l"(d) : "l"(a), "l"(b)); return d;
}
__device__ __forceinline__ ull add2(ull a, ull b) {
    ull d; asm("add.rn.f32x2 %0, %1, %2;" : "=l"(d) : "l"(a), "l"(b)); return d;
}

// load PAIRS u64 from an act row
template<int PAIRS>
__device__ __forceinline__ void ldrowP(const float* p, ull v[PAIRS]) {
    ulonglong2 a = *reinterpret_cast<const ulonglong2*>(p);
    v[0] = a.x; v[1] = a.y;
    if (PAIRS == 3) {
        v[2] = reinterpret_cast<const ull*>(p)[2];
    } else if (PAIRS == 4) {
        ulonglong2 b = reinterpret_cast<const ulonglong2*>(p)[1];
        v[2] = b.x; v[3] = b.y;
    }
}

// C=4 partial GEMM for j-group g. j = 4*NJ4*g + jm + 4*jd ; phys(j) = NJ4*g + jm*Q + jd
// NOTE: jd unroll bounded to 8 to keep the gemm body I-cache-resident
// (full unroll made each loop iteration ~30KB of code > L0/L1.5).
template<int PAIRS, int NJ4, int Q>
__device__ __forceinline__ void gemmC4(const float* __restrict__ Wt, int col0, int g,
                                       const float* sIn, ull acc[4 * PAIRS]) {
#pragma unroll
    for (int jm = 0; jm < 4; ++jm) {
        const float* wp = Wt + (4 * NJ4 * g + jm) * Hd + col0;
        const float* sp = sIn + (NJ4 * g + jm * Q) * PITCH;
#pragma unroll 8
        for (int jd = 0; jd < NJ4; ++jd) {
            float4 w4 = *reinterpret_cast<const float4*>(wp);
            ull v[PAIRS];
            ldrowP<PAIRS>(sp, v);
            ull w0 = pack2(w4.x, w4.x), w1 = pack2(w4.y, w4.y);
            ull w2 = pack2(w4.z, w4.z), w3 = pack2(w4.w, w4.w);
#pragma unroll
            for (int t = 0; t < PAIRS; ++t) {
                acc[t]             = fma2(w0, v[t], acc[t]);
                acc[PAIRS + t]     = fma2(w1, v[t], acc[PAIRS + t]);
                acc[2 * PAIRS + t] = fma2(w2, v[t], acc[2 * PAIRS + t]);
                acc[3 * PAIRS + t] = fma2(w3, v[t], acc[3 * PAIRS + t]);
            }
            wp += 4 * Hd;
            sp += PITCH;
        }
    }
}

// export partials: col c at slot offset c*4 (stride 4 u64 per col, both PAIRS)
template<int PAIRS>
__device__ __forceinline__ void exportP(ull* p, const ull acc[4 * PAIRS]) {
#pragma unroll
    for (int c = 0; c < 4; ++c) {
        ull* b = p + c * 4;
        reinterpret_cast<ulonglong2*>(b)[0] =
            make_ulonglong2(acc[c * PAIRS + 0], acc[c * PAIRS + 1]);
        if (PAIRS == 3) {
            b[2] = acc[c * PAIRS + 2];
        } else {
            reinterpret_cast<ulonglong2*>(b)[1] =
                make_ulonglong2(acc[c * PAIRS + 2], acc[c * PAIRS + 3]);
        }
    }
}

// merge this thread's col (offset g*4 in each exporter slot) across 4 groups
template<int PAIRS>
__device__ __forceinline__ void mergeP(const ull* sRed, int quad, int g, ull m[PAIRS]) {
#pragma unroll
    for (int t = 0; t < PAIRS; ++t) m[t] = 0ull;
#pragma unroll
    for (int gp = 0; gp < 4; ++gp) {
        const ull* p = sRed + (gp * 64 + quad) * SLOT + g * 4;
        ulonglong2 a = reinterpret_cast<const ulonglong2*>(p)[0];
        m[0] = add2(m[0], a.x); m[1] = add2(m[1], a.y);
        if (PAIRS == 3) {
            m[2] = add2(m[2], p[2]);
        } else {
            ulonglong2 b = reinterpret_cast<const ulonglong2*>(p)[1];
            m[2] = add2(m[2], b.x); m[3] = add2(m[3], b.y);
        }
    }
}

template<int PAIRS>
__device__ __forceinline__ void st_slice(float* rowbase, const ull m[PAIRS]) {
    ull* p = reinterpret_cast<ull*>(rowbase);
    reinterpret_cast<ulonglong2*>(p)[0] = make_ulonglong2(m[0], m[1]);
    if (PAIRS == 3) {
        p[2] = m[2];
    } else {
        reinterpret_cast<ulonglong2*>(p)[1] = make_ulonglong2(m[2], m[3]);
    }
}

// ---------------- merged transpose ----------------
__global__ void transpose_all(const float* __restrict__ wh,
                              const float* __restrict__ wout,
                              const float* __restrict__ wx) {
    __shared__ float tile[32][33];
    int b = blockIdx.x;
    const float* in; float* out; int rows, cols, bx;
    if (b < 64)       { in = wh;   out = g_whT;   rows = Hd; cols = Hd;  bx = b; }
    else if (b < 128) { in = wout; out = g_woutT; rows = Hd; cols = Hd;  bx = b - 64; }
    else              { in = wx;   out = g_wxT;   rows = Hd; cols = INd; bx = b - 128; }
    int nbx = cols / 32;
    int c0 = (bx % nbx) * 32, r0 = (bx / nbx) * 32;
    for (int dy = threadIdx.y; dy < 32; dy += 8)
        tile[dy][threadIdx.x] = in[(r0 + dy) * cols + (c0 + threadIdx.x)];
    __syncthreads();
    for (int dy = threadIdx.y; dy < 32; dy += 8)
        out[(c0 + dy) * rows + (r0 + threadIdx.x)] = tile[threadIdx.x][dy];
}

// ---------------- the full pipeline, parameterized on PAIRS (rows = 2*PAIRS) ----------------
template<int PAIRS>
__device__ __forceinline__ void pipeline(
    const float* __restrict__ hin, const float* __restrict__ xin,
    const float* __restrict__ xdin, const float* __restrict__ b0,
    const float* __restrict__ b1, float* __restrict__ out,
    ull* sRed, float* sA, float* sB, float* sXx, float* sXd, int row0) {

    const int ROWSL = 2 * PAIRS;
    const int tid   = threadIdx.x;
    const int warp  = tid >> 5;
    const int lane  = tid & 31;
    const int g     = warp >> 1;                 // j-group 0..3 (warp-uniform)
    const int quad  = ((warp & 1) << 5) + lane;  // 0..63
    const int col0  = quad << 2;
    const int mycol = col0 + g;
    const int myrow = quad + (g << 6);           // phys(mycol)
    ull* myslot = sRed + (g * 64 + quad) * SLOT;

    float bk0 = b0[mycol];
    float bk1 = b1[mycol];

    // ---- stage inputs (transposed + phys-permuted). NTHR == Hd: thread = one j column.
    {
        int pr = (tid >> 2) + ((tid & 3) << 6);
#pragma unroll
        for (int r = 0; r < ROWSL; ++r)
            sA[pr * PITCH + r] = hin[(row0 + r) * Hd + tid];
        if (tid < 2 * INd) {
            int i = tid & 63;
            int px = (i >> 2) + ((i & 3) << 4);
            const float* src = (tid < INd) ? xin : xdin;
            float* dst = (tid < INd) ? sXx : sXd;
#pragma unroll
            for (int r = 0; r < ROWSL; ++r)
                dst[px * PITCH + r] = src[(row0 + r) * INd + i];
        }
    }
    __syncthreads();

    ull gate[PAIRS], dth[PAIRS], hd[PAIRS];
    ull acc[4 * PAIRS];

    // ---- P1: l1 = x@wxT + h@whT + b0 -> gate, relu(sB)
#pragma unroll
    for (int q = 0; q < 4 * PAIRS; ++q) acc[q] = 0ull;
    gemmC4<PAIRS, 4, 16>(g_wxT, col0, g, sXx, acc);
    gemmC4<PAIRS, 16, 64>(g_whT, col0, g, sA, acc);
    exportP<PAIRS>(myslot, acc);
    __syncthreads();
    {
        ull m[PAIRS];
        mergeP<PAIRS>(sRed, quad, g, m);
        ull bp = pack2(bk0, bk0);
        ull relu[PAIRS];
#pragma unroll
        for (int t = 0; t < PAIRS; ++t) {
            m[t] = add2(m[t], bp);
            float a, b; unpack2(m[t], a, b);
            float ga = (a > 0.f) ? 1.f : 0.f;
            float gb = (b > 0.f) ? 1.f : 0.f;
            gate[t] = pack2(ga, gb);
            relu[t] = pack2(ga * a, gb * b);
        }
        st_slice<PAIRS>(sB + myrow * PITCH, relu);
    }
    __syncthreads();

    // ---- P2: uu = xdot@wxT ; gated-u -> sA
#pragma unroll
    for (int q = 0; q < 4 * PAIRS; ++q) acc[q] = 0ull;
    gemmC4<PAIRS, 4, 16>(g_wxT, col0, g, sXd, acc);
    exportP<PAIRS>(myslot, acc);
    __syncthreads();
    {
        ull m[PAIRS];
        mergeP<PAIRS>(sRed, quad, g, m);
#pragma unroll
        for (int t = 0; t < PAIRS; ++t) m[t] = mul2(m[t], gate[t]);
        st_slice<PAIRS>(sA + myrow * PITCH, m);
    }
    __syncthreads();

    // ---- P3: lout = relu@woutT + b1 -> dth
#pragma unroll
    for (int q = 0; q < 4 * PAIRS; ++q) acc[q] = 0ull;
    gemmC4<PAIRS, 16, 64>(g_woutT, col0, g, sB, acc);
    exportP<PAIRS>(myslot, acc);
    __syncthreads();
    {
        ull m[PAIRS];
        mergeP<PAIRS>(sRed, quad, g, m);
        ull bp = pack2(bk1, bk1);
#pragma unroll
        for (int t = 0; t < PAIRS; ++t) {
            ull L = add2(m[t], bp);
            float a, b; unpack2(L, a, b);
            float ta = tanhf(a), tb = tanhf(b);
            dth[t] = pack2(1.f - ta * ta, 1.f - tb * tb);
        }
    }
    __syncthreads();

    // ---- P4: jx = gated-u@woutT ; curr = dth*jx -> sA ; hdot = curr
#pragma unroll
    for (int q = 0; q < 4 * PAIRS; ++q) acc[q] = 0ull;
    gemmC4<PAIRS, 16, 64>(g_woutT, col0, g, sA, acc);
    exportP<PAIRS>(myslot, acc);
    __syncthreads();
    {
        ull m[PAIRS];
        mergeP<PAIRS>(sRed, quad, g, m);
#pragma unroll
        for (int t = 0; t < PAIRS; ++t) m[t] = mul2(m[t], dth[t]);
        st_slice<PAIRS>(sA + myrow * PITCH, m);
#pragma unroll
        for (int t = 0; t < PAIRS; ++t) hd[t] = m[t];
    }
    __syncthreads();

    // ---- 8 Jh-power iterations (runtime loop: keep code size small)
#pragma unroll 1
    for (int it = 0; it < KTERMS; ++it) {
#pragma unroll
        for (int q = 0; q < 4 * PAIRS; ++q) acc[q] = 0ull;
        gemmC4<PAIRS, 16, 64>(g_whT, col0, g, sA, acc);
        exportP<PAIRS>(myslot, acc);
        __syncthreads();
        {
            ull m[PAIRS];
            mergeP<PAIRS>(sRed, quad, g, m);
#pragma unroll
            for (int t = 0; t < PAIRS; ++t) m[t] = mul2(m[t], gate[t]);
            st_slice<PAIRS>(sB + myrow * PITCH, m);
        }
        __syncthreads();
#pragma unroll
        for (int q = 0; q < 4 * PAIRS; ++q) acc[q] = 0ull;
        gemmC4<PAIRS, 16, 64>(g_woutT, col0, g, sB, acc);
        exportP<PAIRS>(myslot, acc);
        __syncthreads();
        {
            ull m[PAIRS];
            mergeP<PAIRS>(sRed, quad, g, m);
#pragma unroll
            for (int t = 0; t < PAIRS; ++t) m[t] = mul2(m[t], dth[t]);
            st_slice<PAIRS>(sA + myrow * PITCH, m);
#pragma unroll
            for (int t = 0; t < PAIRS; ++t) hd[t] = add2(hd[t], m[t]);
        }
        __syncthreads();
    }

    // ---- write h_dot
#pragma unroll
    for (int t = 0; t < PAIRS; ++t) {
        float a, b; unpack2(hd[t], a, b);
        out[(row0 + 2 * t)     * Hd + mycol] = a;
        out[(row0 + 2 * t + 1) * Hd + mycol] = b;
    }
}

// ---------------- fused kernel: 296 CTAs, one wave, 4+3 pairs per SM ----------------
__global__ void __launch_bounds__(NTHR, 2)
fused_kernel(const float* __restrict__ hin, const float* __restrict__ xin,
             const float* __restrict__ xdin, const float* __restrict__ b0,
             const float* __restrict__ b1, float* __restrict__ out) {
    extern __shared__ __align__(16) char smraw[];
    ull*   sRed = reinterpret_cast<ull*>(smraw);
    float* sA   = reinterpret_cast<float*>(sRed + NTHR * SLOT);
    float* sB   = sA + Hd * PITCH;
    float* sXx  = sB + Hd * PITCH;
    float* sXd  = sXx + INd * PITCH;

    int bid = blockIdx.x;
    if (bid < 148) {
        pipeline<4>(hin, xin, xdin, b0, b1, out, sRed, sA, sB, sXx, sXd, bid * 8);
    } else {
        int row0 = 148 * 8 + (bid - 148) * 6;
        if (row0 + 6 > Bsz) return;               // tail CTAs (rows >= 2048) idle
        pipeline<3>(hin, xin, xdin, b0, b1, out, sRed, sA, sB, sXx, sXd, row0);
    }
}

#define SMEM_BYTES (NTHR * SLOT * 8 + (2 * Hd + 2 * INd) * PITCH * 4)

extern "C" void kernel_launch(void* const* d_in, const int* in_sizes, int n_in,
                              void* d_out, int out_size) {
    (void)in_sizes; (void)n_in; (void)out_size;
    const float* h_   = (const float*)d_in[0];
    const float* x    = (const float*)d_in[1];
    const float* xdot = (const float*)d_in[2];
    const float* wx   = (const float*)d_in[3];
    const float* wh   = (const float*)d_in[4];
    const float* wout = (const float*)d_in[5];
    const float* b0   = (const float*)d_in[6];
    const float* b1   = (const float*)d_in[7];
    float* out = (float*)d_out;

    cudaFuncSetAttribute(fused_kernel, cudaFuncAttributeMaxDynamicSharedMemorySize, SMEM_BYTES);
    transpose_all<<<144, dim3(32, 8)>>>(wh, wout, wx);
    fused_kernel<<<296, NTHR, SMEM_BYTES>>>(h_, x, xdot, b0, b1, out);
}